// round 15
// baseline (speedup 1.0000x reference)
#include <cuda_runtime.h>

#define S 2048
#define DM 512
#define NI 13
#define NC 117

typedef unsigned long long ull;

// ---------------- scratch ----------------
__device__ float  g_Wp[DM * 128];            // padded W, [k][128]
__device__ float4 g_plin[NI * S];            // {x0, y0, cw, sw} lin channel, [i][a]
__device__ float4 g_pang[NI * S];            // ang channel
__device__ float  g_base[NI * S];            // min + noise_bias, [i][b]
__device__ float  g_partial[16 * NI * S];    // [ca][i][b]
__device__ int    g_cnt[NI * 16];            // per-(i,cb) counters (self-resetting)

// ---------------- packed f32x2 helpers: in-place forms (no result movs) ----
#define MUL2F(d, a, b)  asm("mul.rn.f32x2 %0, %1, %2;"      : "=l"(d) : "l"(a), "l"(b))
#define ADD2F(d, a, b)  asm("add.rn.f32x2 %0, %1, %2;"      : "=l"(d) : "l"(a), "l"(b))
#define FMA2F(d, a, b, c) asm("fma.rn.f32x2 %0, %1, %2, %3;" : "=l"(d) : "l"(a), "l"(b), "l"(c))
#define FMA2_ACC(d, a, b) asm("fma.rn.f32x2 %0, %1, %2, %0;" : "+l"(d) : "l"(a), "l"(b))
#define ADD2_IP(d, a)   asm("add.rn.f32x2 %0, %0, %1;"      : "+l"(d) : "l"(a))

__device__ __forceinline__ ull pk2(float lo, float hi) {
    ull r; asm("mov.b64 %0, {%1,%2};" : "=l"(r) : "f"(lo), "f"(hi)); return r;
}
__device__ __forceinline__ void upk2(ull v, float& lo, float& hi) {
    asm("mov.b64 {%0,%1}, %2;" : "=f"(lo), "=f"(hi) : "l"(v));
}
__device__ __forceinline__ ull fma2(ull a, ull b, ull c) {
    ull d; FMA2F(d, a, b, c); return d;
}
__device__ __forceinline__ ull mul2(ull a, ull b) {
    ull d; MUL2F(d, a, b); return d;
}
__device__ __forceinline__ ull add2(ull a, ull b) {
    ull d; ADD2F(d, a, b); return d;
}
__device__ __forceinline__ ull neg2(ull a) { return a ^ 0x8000000080000000ULL; }

__device__ __forceinline__ float softplus_f(float x) {
    return fmaxf(x, 0.0f) + log1pf(expf(-fabsf(x)));
}

// branchless packed complex pow: (rx,ry) = (bx,by)^e, e < 2048  (init only)
__device__ __forceinline__ void cpow2(ull bx, ull by, unsigned e, ull& rx, ull& ry) {
    rx = pk2(1.0f, 1.0f); ry = pk2(0.0f, 0.0f);
    #pragma unroll
    for (int it = 0; it < 11; it++) {
        ull tx = fma2(rx, bx, neg2(mul2(ry, by)));
        ull ty = fma2(rx, by, mul2(ry, bx));
        bool m = (e & 1u) != 0u;
        rx = m ? tx : rx;
        ry = m ? ty : ry;
        e >>= 1;
        ull t2 = mul2(bx, by);
        bx = fma2(bx, bx, neg2(mul2(by, by)));
        by = add2(t2, t2);
    }
}

// ---------------- 0) pad W (float4 stores) + zero counters ----------------
__global__ void wprep_kernel(const float* __restrict__ W) {
    int idx4 = blockIdx.x * 256 + threadIdx.x;   // DM*128/4 = 16384
    int k  = idx4 >> 5;
    int c0 = (idx4 & 31) * 4;
    const float* Wr = W + k * NC;
    float4 v;
    v.x = (c0 + 0 < NC) ? Wr[c0 + 0] : 0.0f;
    v.y = (c0 + 1 < NC) ? Wr[c0 + 1] : 0.0f;
    v.z = (c0 + 2 < NC) ? Wr[c0 + 2] : 0.0f;
    v.w = (c0 + 3 < NC) ? Wr[c0 + 3] : 0.0f;
    ((float4*)g_Wp)[idx4] = v;
    if (idx4 < NI * 16) g_cnt[idx4] = 0;
}

// ---------------- 1) fused LN + GEMM(split-K) + param transform ----------------
// 128 blocks x 256 threads. Block = 16 tokens.
#define XROW 18
__global__ __launch_bounds__(256) void gemm_fused(
    const float* __restrict__ h, const float* __restrict__ mn,
    const float* __restrict__ lw, const float* __restrict__ lb,
    const float* __restrict__ bias)
{
    __shared__ __align__(16) float xsT[DM * XROW];   // 36.9 KB; reused as ps4 later

    int t  = threadIdx.x;
    int s0 = blockIdx.x * 16;

    // ---- LayerNorm: 16 threads per row, 16 rows; store TRANSPOSED ----
    {
        int r = t >> 4, sub = t & 15;
        const float4* h4 = (const float4*)h;
        float4 v[8];
        float sum = 0.f, sq = 0.f;
        #pragma unroll
        for (int q = 0; q < 8; q++) {
            v[q] = h4[(s0 + r) * (DM / 4) + sub + q * 16];
            sum += v[q].x + v[q].y + v[q].z + v[q].w;
            sq  += v[q].x * v[q].x + v[q].y * v[q].y + v[q].z * v[q].z + v[q].w * v[q].w;
        }
        #pragma unroll
        for (int o = 8; o; o >>= 1) {
            sum += __shfl_xor_sync(0xffffffffu, sum, o);
            sq  += __shfl_xor_sync(0xffffffffu, sq,  o);
        }
        float mu   = sum * (1.0f / DM);
        float var  = sq * (1.0f / DM) - mu * mu;
        float rstd = rsqrtf(var + 1e-5f);
        const float4* lw4 = (const float4*)lw;
        const float4* lb4 = (const float4*)lb;
        #pragma unroll
        for (int q = 0; q < 8; q++) {
            float4 wv = lw4[sub + q * 16], bv = lb4[sub + q * 16];
            int k0 = (sub + q * 16) * 4;
            xsT[(k0 + 0) * XROW + r] = (v[q].x - mu) * rstd * wv.x + bv.x;
            xsT[(k0 + 1) * XROW + r] = (v[q].y - mu) * rstd * wv.y + bv.y;
            xsT[(k0 + 2) * XROW + r] = (v[q].z - mu) * rstd * wv.z + bv.z;
            xsT[(k0 + 3) * XROW + r] = (v[q].w - mu) * rstd * wv.w + bv.w;
        }
    }
    __syncthreads();

    // ---- GEMM: warp = 8 tokens (4 pairs) x 128 cols, over its K quarter ----
    int lane = t & 31, w = t >> 5;
    int tokg = (w & 1) * 8, kq = w >> 1;
    ull A[4][4];
    #pragma unroll
    for (int p = 0; p < 4; p++)
        #pragma unroll
        for (int q = 0; q < 4; q++) A[p][q] = 0ULL;

    const float4* Wp4 = (const float4*)g_Wp;
    int kbeg = kq * 128, kend = kbeg + 128;
    #pragma unroll 8
    for (int k = kbeg; k < kend; k++) {
        ull x01 = *(const ull*)&xsT[k * XROW + tokg + 0];
        ull x23 = *(const ull*)&xsT[k * XROW + tokg + 2];
        ull x45 = *(const ull*)&xsT[k * XROW + tokg + 4];
        ull x67 = *(const ull*)&xsT[k * XROW + tokg + 6];
        float4 wv = Wp4[k * 32 + lane];
        ull wd0 = pk2(wv.x, wv.x), wd1 = pk2(wv.y, wv.y);
        ull wd2 = pk2(wv.z, wv.z), wd3 = pk2(wv.w, wv.w);
        FMA2_ACC(A[0][0], x01, wd0); FMA2_ACC(A[0][1], x01, wd1);
        FMA2_ACC(A[0][2], x01, wd2); FMA2_ACC(A[0][3], x01, wd3);
        FMA2_ACC(A[1][0], x23, wd0); FMA2_ACC(A[1][1], x23, wd1);
        FMA2_ACC(A[1][2], x23, wd2); FMA2_ACC(A[1][3], x23, wd3);
        FMA2_ACC(A[2][0], x45, wd0); FMA2_ACC(A[2][1], x45, wd1);
        FMA2_ACC(A[2][2], x45, wd2); FMA2_ACC(A[2][3], x45, wd3);
        FMA2_ACC(A[3][0], x67, wd0); FMA2_ACC(A[3][1], x67, wd1);
        FMA2_ACC(A[3][2], x67, wd2); FMA2_ACC(A[3][3], x67, wd3);
    }
    __syncthreads();   // x no longer needed; reuse xsT as ps4[4][16][128]

    // ---- write per-quarter partials (c = 4*lane + q) ----
    float* ps4 = xsT;
    #pragma unroll
    for (int p = 0; p < 4; p++) {
        #pragma unroll
        for (int q = 0; q < 4; q++) {
            float e0, e1; upk2(A[p][q], e0, e1);
            int c = 4 * lane + q;
            int tok0 = tokg + 2 * p;
            ps4[(kq * 16 + tok0) * 128 + c]     = e0;
            ps4[(kq * 16 + tok0 + 1) * 128 + c] = e1;
        }
    }
    __syncthreads();

    // ---- sum 4 quarters into quarter 0 (ps[tok][c]) ----
    {
        float4* q0 = (float4*)ps4;
        #pragma unroll
        for (int j = 0; j < 2; j++) {
            int u4 = t * 2 + j;                 // 512 float4 slots = 16x128
            float4 a = q0[u4];
            float4 b = q0[512 + u4];
            float4 c = q0[1024 + u4];
            float4 d = q0[1536 + u4];
            a.x += b.x + c.x + d.x;
            a.y += b.y + c.y + d.y;
            a.z += b.z + c.z + d.z;
            a.w += b.w + c.w + d.w;
            q0[u4] = a;
        }
    }
    __syncthreads();

    // ---- param transform: 16 tokens x 13 imus x 2 channels = 416 units ----
    float* ps = ps4;
    for (int u = t; u < 16 * NI * 2; u += 256) {
        int r   = u / (2 * NI);
        int rem = u - r * 2 * NI;
        int i = rem >> 1, ch = rem & 1;
        int s = s0 + r;
        const float* P = ps + r * 128;
        int ck  = (ch ? 2 : 0) * NI + i;
        int cd  = (ch ? 3 : 1) * NI + i;
        int cc  = (ch ? 5 : 4) * NI + i;
        int cph = (ch ? 7 : 6) * NI + i;
        float pk  = P[ck]  + bias[ck];
        float pd  = P[cd]  + bias[cd];
        float pc  = P[cc]  + bias[cc];
        float pph = P[cph] + bias[cph];

        float d  = sqrtf(pd * pd + 1e-5f);
        float sp = softplus_f(pk);
        float kk = d * d * 0.25f + sp;
        float om = 0.5f * sqrtf(fmaxf(4.0f * kk - d * d, 0.0f));
        float dec = expf(-0.5f * d);
        float so, co; sincosf(om, &so, &co);
        float sph, cph_; sincosf(pph, &sph, &cph_);
        float4 v = make_float4(pc * cph_, pc * sph, dec * co, dec * so);
        if (ch) g_pang[i * S + s] = v;
        else {
            g_plin[i * S + s] = v;
            int c8 = 8 * NI + i;
            g_base[i * S + s] = mn[0] + P[c8] + bias[c8];
        }
    }
}

// ---------------- 2) triangular sweep + fused final fold ----------------
// smem: ull buffer 32 b-slots x stride 33 = 8448 B.
// Store: sbuf[bb*33 + lane]  imm-offset STS.64, bank (bb+lane)&31, conflict-free.
// Fold:  lane reads row lane: sbuf[lane*33 + c], bank (lane+c)&31, conflict-free.

__device__ __forceinline__ void fold32(const ull* sbuf, float* pout, int lane) {
    const ull* row = sbuf + lane * 33;
    ull a0 = 0ULL, a1 = 0ULL, a2 = 0ULL, a3 = 0ULL;
    #pragma unroll
    for (int c = 0; c < 32; c += 4) {
        ull v0 = row[c + 0]; ADD2_IP(a0, v0);
        ull v1 = row[c + 1]; ADD2_IP(a1, v1);
        ull v2 = row[c + 2]; ADD2_IP(a2, v2);
        ull v3 = row[c + 3]; ADD2_IP(a3, v3);
    }
    ull u, v2s, acc;
    ADD2F(u, a0, a1);
    ADD2F(v2s, a2, a3);
    ADD2F(acc, u, v2s);
    float lo, hi; upk2(acc, lo, hi);
    pout[lane] = lo + hi;
}

// steady tile: 128 a's, 128 b's, double-step (emit b, b+1; rotate by w^2)
__device__ __forceinline__ void run_full(int a0, int b0, int i, float* pout,
                                         int lane, ull* sbuf) {
    ull X[4], Y[4], CW[4], SW[4], CW2[4], SW2[4], NSW2[4];
    #pragma unroll
    for (int j = 0; j < 4; j++) {
        int a = a0 + j * 32 + lane;
        float4 pl = g_plin[i * S + a];
        float4 pa = g_pang[i * S + a];
        CW[j] = pk2(pl.z, pa.z);
        SW[j] = pk2(pl.w, pa.w);
        ull t2 = mul2(CW[j], SW[j]);
        CW2[j]  = fma2(CW[j], CW[j], neg2(mul2(SW[j], SW[j])));
        SW2[j]  = add2(t2, t2);
        NSW2[j] = neg2(SW2[j]);
        ull rx, ry;
        cpow2(CW[j], SW[j], (unsigned)(b0 - a), rx, ry);
        ull x0 = pk2(pl.x, pa.x), y0 = pk2(pl.y, pa.y);
        X[j] = fma2(x0, rx, neg2(mul2(y0, ry)));
        Y[j] = fma2(x0, ry, mul2(y0, rx));
    }
    #pragma unroll 1
    for (int chunk = 0; chunk < 4; chunk++) {
        #pragma unroll
        for (int it = 0; it < 16; it++) {
            int bb0 = it * 2;
            // sA = (Y0+Y1) + (Y2+Y3)
            ull u01, u23, sA;
            ADD2F(u01, Y[0], Y[1]);
            ADD2F(u23, Y[2], Y[3]);
            ADD2F(sA, u01, u23);
            sbuf[bb0 * 33 + lane] = sA;
            // sB = sum_j (X*SW + Y*CW)
            ull m0, m1, m2, m3, v0, v1, v2, v3;
            MUL2F(m0, Y[0], CW[0]); FMA2F(v0, X[0], SW[0], m0);
            MUL2F(m1, Y[1], CW[1]); FMA2F(v1, X[1], SW[1], m1);
            MUL2F(m2, Y[2], CW[2]); FMA2F(v2, X[2], SW[2], m2);
            MUL2F(m3, Y[3], CW[3]); FMA2F(v3, X[3], SW[3], m3);
            ull w01, w23, sB;
            ADD2F(w01, v0, v1);
            ADD2F(w23, v2, v3);
            ADD2F(sB, w01, w23);
            sbuf[(bb0 + 1) * 33 + lane] = sB;
            // rotate by w^2: X = X*CW2 + Y*NSW2 ; Y = Y*CW2 + X_old*SW2
            #pragma unroll
            for (int j = 0; j < 4; j++) {
                ull t1, t2b;
                MUL2F(t1, Y[j], NSW2[j]);
                MUL2F(t2b, X[j], SW2[j]);
                asm("fma.rn.f32x2 %0, %0, %1, %2;" : "+l"(X[j]) : "l"(CW2[j]), "l"(t1));
                asm("fma.rn.f32x2 %0, %0, %1, %2;" : "+l"(Y[j]) : "l"(CW2[j]), "l"(t2b));
            }
        }
        __syncwarp();
        fold32(sbuf, pout + chunk * 32, lane);
        __syncwarp();
    }
}

// diagonal tile: 128 a's, 128 single steps with birth predicate
__device__ __forceinline__ void run_diag(int b0, int i, float* pout,
                                         int lane, ull* sbuf) {
    ull X[4], Y[4], CW[4], SW[4], NSW[4], X0[4], Y0[4];
    int aj[4];
    #pragma unroll
    for (int j = 0; j < 4; j++) {
        int a = b0 + j * 32 + lane;
        aj[j] = a;
        float4 pl = g_plin[i * S + a];
        float4 pa = g_pang[i * S + a];
        CW[j]  = pk2(pl.z, pa.z);
        SW[j]  = pk2(pl.w, pa.w);
        NSW[j] = neg2(SW[j]);
        X0[j] = pk2(pl.x, pa.x);
        Y0[j] = pk2(pl.y, pa.y);
        X[j] = 0ULL; Y[j] = 0ULL;
    }
    #pragma unroll 1
    for (int chunk = 0; chunk < 4; chunk++) {
        #pragma unroll
        for (int bb = 0; bb < 32; bb++) {
            int b = b0 + chunk * 32 + bb;
            #pragma unroll
            for (int j = 0; j < 4; j++) {
                bool hit = (b == aj[j]);
                X[j] = hit ? X0[j] : X[j];
                Y[j] = hit ? Y0[j] : Y[j];
            }
            ull u01, u23, sA;
            ADD2F(u01, Y[0], Y[1]);
            ADD2F(u23, Y[2], Y[3]);
            ADD2F(sA, u01, u23);
            sbuf[bb * 33 + lane] = sA;
            #pragma unroll
            for (int j = 0; j < 4; j++) {
                ull t1, t2;
                MUL2F(t1, Y[j], NSW[j]);
                MUL2F(t2, X[j], SW[j]);
                asm("fma.rn.f32x2 %0, %0, %1, %2;" : "+l"(X[j]) : "l"(CW[j]), "l"(t1));
                asm("fma.rn.f32x2 %0, %0, %1, %2;" : "+l"(Y[j]) : "l"(CW[j]), "l"(t2));
            }
        }
        __syncwarp();
        fold32(sbuf, pout + chunk * 32, lane);
        __syncwarp();
    }
}

// grid (136, 13): slot -> (ca, cb) triangular, ca <= cb. Last tile of a
// (i, cb) column (cb+1 tiles) folds base + partials -> out, resets counter.
__global__ __launch_bounds__(32) void sweep_kernel(float* __restrict__ out) {
    __shared__ ull sbuf[32 * 33];   // 8448 B
    int slot = blockIdx.x, i = blockIdx.y;
    int lane = threadIdx.x;
    int s = slot, cb = 0;
    while (s > cb) { s -= (cb + 1); cb++; }
    int ca = s;
    float* pout = g_partial + (ca * NI + i) * S + cb * 128;
    if (ca == cb) run_diag(cb * 128, i, pout, lane, sbuf);
    else          run_full(ca * 128, cb * 128, i, pout, lane, sbuf);

    // fused fold: last tile of (i, cb) column writes the output
    __threadfence();
    int last = 0;
    if (lane == 0)
        last = (atomicAdd(&g_cnt[i * 16 + cb], 1) == cb);
    last = __shfl_sync(0xffffffffu, last, 0);
    if (last) {
        __threadfence();
        #pragma unroll
        for (int g = 0; g < 4; g++) {
            int b = cb * 128 + g * 32 + lane;
            float acc = g_base[i * S + b];
            #pragma unroll
            for (int c2 = 0; c2 < 16; c2++)
                if (c2 <= cb) acc += g_partial[(c2 * NI + i) * S + b];
            out[i * S + b] = acc;
        }
        if (lane == 0) g_cnt[i * 16 + cb] = 0;   // self-reset for next replay
    }
}

// ---------------- launch ----------------
extern "C" void kernel_launch(void* const* d_in, const int* in_sizes, int n_in,
                              void* d_out, int out_size) {
    const float* h    = (const float*)d_in[0];
    const float* mn   = (const float*)d_in[1];
    const float* lw   = (const float*)d_in[2];
    const float* lb   = (const float*)d_in[3];
    const float* W    = (const float*)d_in[4];
    const float* bias = (const float*)d_in[5];
    float* out = (float*)d_out;

    wprep_kernel<<<64, 256>>>(W);
    gemm_fused<<<S / 16, 256>>>(h, mn, lw, lb, bias);
    dim3 g(136, NI);
    sweep_kernel<<<g, 32>>>(out);
}

// round 16
// speedup vs baseline: 1.1721x; 1.1721x over previous
#include <cuda_runtime.h>

#define S 2048
#define DM 512
#define NI 13
#define NC 117

typedef unsigned long long ull;

// ---------------- scratch ----------------
__device__ float  g_Wp[DM * 128];            // padded W, [k][128]
__device__ float4 g_plin[NI * S];            // {x0, y0, cw, sw} lin channel, [i][a]
__device__ float4 g_pang[NI * S];            // ang channel
__device__ float  g_base[NI * S];            // min + noise_bias, [i][b]
__device__ float  g_partial[16 * NI * S];    // [ca][i][b]
__device__ int    g_cnt[NI * 16];            // per-(i,cb) counters (self-resetting)

// ---------------- packed f32x2 helpers ----------------
#define MUL2F(d, a, b)  asm("mul.rn.f32x2 %0, %1, %2;"      : "=l"(d) : "l"(a), "l"(b))
#define ADD2F(d, a, b)  asm("add.rn.f32x2 %0, %1, %2;"      : "=l"(d) : "l"(a), "l"(b))
#define FMA2F(d, a, b, c) asm("fma.rn.f32x2 %0, %1, %2, %3;" : "=l"(d) : "l"(a), "l"(b), "l"(c))
#define FMA2_ACC(d, a, b) asm("fma.rn.f32x2 %0, %1, %2, %0;" : "+l"(d) : "l"(a), "l"(b))
#define ADD2_IP(d, a)   asm("add.rn.f32x2 %0, %0, %1;"      : "+l"(d) : "l"(a))

__device__ __forceinline__ ull pk2(float lo, float hi) {
    ull r; asm("mov.b64 %0, {%1,%2};" : "=l"(r) : "f"(lo), "f"(hi)); return r;
}
__device__ __forceinline__ void upk2(ull v, float& lo, float& hi) {
    asm("mov.b64 {%0,%1}, %2;" : "=f"(lo), "=f"(hi) : "l"(v));
}
__device__ __forceinline__ ull fma2(ull a, ull b, ull c) {
    ull d; FMA2F(d, a, b, c); return d;
}
__device__ __forceinline__ ull mul2(ull a, ull b) {
    ull d; MUL2F(d, a, b); return d;
}
__device__ __forceinline__ ull add2(ull a, ull b) {
    ull d; ADD2F(d, a, b); return d;
}
__device__ __forceinline__ ull neg2(ull a) { return a ^ 0x8000000080000000ULL; }

__device__ __forceinline__ float softplus_f(float x) {
    return fmaxf(x, 0.0f) + log1pf(expf(-fabsf(x)));
}

// branchless packed complex pow: (rx,ry) = (bx,by)^e, e < 2048  (init only)
__device__ __forceinline__ void cpow2(ull bx, ull by, unsigned e, ull& rx, ull& ry) {
    rx = pk2(1.0f, 1.0f); ry = pk2(0.0f, 0.0f);
    #pragma unroll
    for (int it = 0; it < 11; it++) {
        ull tx = fma2(rx, bx, neg2(mul2(ry, by)));
        ull ty = fma2(rx, by, mul2(ry, bx));
        bool m = (e & 1u) != 0u;
        rx = m ? tx : rx;
        ry = m ? ty : ry;
        e >>= 1;
        ull t2 = mul2(bx, by);
        bx = fma2(bx, bx, neg2(mul2(by, by)));
        by = add2(t2, t2);
    }
}

// ---------------- 0) pad W (float4 stores) + zero counters ----------------
__global__ void wprep_kernel(const float* __restrict__ W) {
    int idx4 = blockIdx.x * 256 + threadIdx.x;   // DM*128/4 = 16384
    int k  = idx4 >> 5;
    int c0 = (idx4 & 31) * 4;
    const float* Wr = W + k * NC;
    float4 v;
    v.x = (c0 + 0 < NC) ? Wr[c0 + 0] : 0.0f;
    v.y = (c0 + 1 < NC) ? Wr[c0 + 1] : 0.0f;
    v.z = (c0 + 2 < NC) ? Wr[c0 + 2] : 0.0f;
    v.w = (c0 + 3 < NC) ? Wr[c0 + 3] : 0.0f;
    ((float4*)g_Wp)[idx4] = v;
    if (idx4 < NI * 16) g_cnt[idx4] = 0;
}

// ---------------- 1) fused LN + GEMM(split-K x8) + param transform ------------
// 128 blocks x 512 threads. Block = 16 tokens. Warp w (0..15):
//   tokg = (w&1)*8 tokens, kq = w>>1 -> K-eighth of 64 k.
#define XROW 18
__global__ __launch_bounds__(512) void gemm_fused(
    const float* __restrict__ h, const float* __restrict__ mn,
    const float* __restrict__ lw, const float* __restrict__ lb,
    const float* __restrict__ bias)
{
    __shared__ __align__(16) float xsT[DM * XROW];   // 36.9 KB; reused as ps4 later

    int t  = threadIdx.x;
    int s0 = blockIdx.x * 16;

    // ---- LayerNorm: one warp per row, 16 rows; store TRANSPOSED ----
    {
        int r = t >> 5, sub = t & 31;
        const float4* h4 = (const float4*)h;
        float4 v[4];
        float sum = 0.f, sq = 0.f;
        #pragma unroll
        for (int q = 0; q < 4; q++) {
            v[q] = h4[(s0 + r) * (DM / 4) + sub + q * 32];
            sum += v[q].x + v[q].y + v[q].z + v[q].w;
            sq  += v[q].x * v[q].x + v[q].y * v[q].y + v[q].z * v[q].z + v[q].w * v[q].w;
        }
        #pragma unroll
        for (int o = 16; o; o >>= 1) {
            sum += __shfl_xor_sync(0xffffffffu, sum, o);
            sq  += __shfl_xor_sync(0xffffffffu, sq,  o);
        }
        float mu   = sum * (1.0f / DM);
        float var  = sq * (1.0f / DM) - mu * mu;
        float rstd = rsqrtf(var + 1e-5f);
        const float4* lw4 = (const float4*)lw;
        const float4* lb4 = (const float4*)lb;
        #pragma unroll
        for (int q = 0; q < 4; q++) {
            float4 wv = lw4[sub + q * 32], bv = lb4[sub + q * 32];
            int k0 = (sub + q * 32) * 4;
            xsT[(k0 + 0) * XROW + r] = (v[q].x - mu) * rstd * wv.x + bv.x;
            xsT[(k0 + 1) * XROW + r] = (v[q].y - mu) * rstd * wv.y + bv.y;
            xsT[(k0 + 2) * XROW + r] = (v[q].z - mu) * rstd * wv.z + bv.z;
            xsT[(k0 + 3) * XROW + r] = (v[q].w - mu) * rstd * wv.w + bv.w;
        }
    }
    __syncthreads();

    // ---- GEMM: warp = 8 tokens (4 pairs) x 128 cols, over its K-eighth ----
    int lane = t & 31, w = t >> 5;
    int tokg = (w & 1) * 8, kq = w >> 1;   // kq 0..7
    ull A[4][4];
    #pragma unroll
    for (int p = 0; p < 4; p++)
        #pragma unroll
        for (int q = 0; q < 4; q++) A[p][q] = 0ULL;

    const float4* Wp4 = (const float4*)g_Wp;
    int kbeg = kq * 64, kend = kbeg + 64;
    #pragma unroll 8
    for (int k = kbeg; k < kend; k++) {
        ull x01 = *(const ull*)&xsT[k * XROW + tokg + 0];
        ull x23 = *(const ull*)&xsT[k * XROW + tokg + 2];
        ull x45 = *(const ull*)&xsT[k * XROW + tokg + 4];
        ull x67 = *(const ull*)&xsT[k * XROW + tokg + 6];
        float4 wv = Wp4[k * 32 + lane];
        ull wd0 = pk2(wv.x, wv.x), wd1 = pk2(wv.y, wv.y);
        ull wd2 = pk2(wv.z, wv.z), wd3 = pk2(wv.w, wv.w);
        FMA2_ACC(A[0][0], x01, wd0); FMA2_ACC(A[0][1], x01, wd1);
        FMA2_ACC(A[0][2], x01, wd2); FMA2_ACC(A[0][3], x01, wd3);
        FMA2_ACC(A[1][0], x23, wd0); FMA2_ACC(A[1][1], x23, wd1);
        FMA2_ACC(A[1][2], x23, wd2); FMA2_ACC(A[1][3], x23, wd3);
        FMA2_ACC(A[2][0], x45, wd0); FMA2_ACC(A[2][1], x45, wd1);
        FMA2_ACC(A[2][2], x45, wd2); FMA2_ACC(A[2][3], x45, wd3);
        FMA2_ACC(A[3][0], x67, wd0); FMA2_ACC(A[3][1], x67, wd1);
        FMA2_ACC(A[3][2], x67, wd2); FMA2_ACC(A[3][3], x67, wd3);
    }
    __syncthreads();   // x no longer needed; reuse xsT as ps4[4][16][128]

    // ---- combine round 1: kq 0..3 store per-quarter partials ----
    float* ps4 = xsT;
    if (kq < 4) {
        #pragma unroll
        for (int p = 0; p < 4; p++) {
            #pragma unroll
            for (int q = 0; q < 4; q++) {
                float e0, e1; upk2(A[p][q], e0, e1);
                int c = 4 * lane + q;
                int tok0 = tokg + 2 * p;
                ps4[(kq * 16 + tok0) * 128 + c]     = e0;
                ps4[(kq * 16 + tok0 + 1) * 128 + c] = e1;
            }
        }
    }
    __syncthreads();
    // ---- combine round 2: kq 4..7 add into slots 0..3 ----
    if (kq >= 4) {
        int slot = kq - 4;
        #pragma unroll
        for (int p = 0; p < 4; p++) {
            #pragma unroll
            for (int q = 0; q < 4; q++) {
                float e0, e1; upk2(A[p][q], e0, e1);
                int c = 4 * lane + q;
                int tok0 = tokg + 2 * p;
                ps4[(slot * 16 + tok0) * 128 + c]     += e0;
                ps4[(slot * 16 + tok0 + 1) * 128 + c] += e1;
            }
        }
    }
    __syncthreads();

    // ---- sum 4 slots into slot 0 (ps[tok][c]); 2048 float4 over 512 thr ----
    {
        float4* q0 = (float4*)ps4;
        float4 a = q0[t];
        float4 b = q0[512 + t];
        float4 c = q0[1024 + t];
        float4 d = q0[1536 + t];
        a.x += b.x + c.x + d.x;
        a.y += b.y + c.y + d.y;
        a.z += b.z + c.z + d.z;
        a.w += b.w + c.w + d.w;
        q0[t] = a;
    }
    __syncthreads();

    // ---- param transform: 16 tokens x 13 imus x 2 channels = 416 units ----
    float* ps = ps4;
    if (t < 16 * NI * 2) {
        int u = t;
        int r   = u / (2 * NI);
        int rem = u - r * 2 * NI;
        int i = rem >> 1, ch = rem & 1;
        int s = s0 + r;
        const float* P = ps + r * 128;
        int ck  = (ch ? 2 : 0) * NI + i;
        int cd  = (ch ? 3 : 1) * NI + i;
        int cc  = (ch ? 5 : 4) * NI + i;
        int cph = (ch ? 7 : 6) * NI + i;
        float pk  = P[ck]  + bias[ck];
        float pd  = P[cd]  + bias[cd];
        float pc  = P[cc]  + bias[cc];
        float pph = P[cph] + bias[cph];

        float d  = sqrtf(pd * pd + 1e-5f);
        float sp = softplus_f(pk);
        float kk = d * d * 0.25f + sp;
        float om = 0.5f * sqrtf(fmaxf(4.0f * kk - d * d, 0.0f));
        float dec = expf(-0.5f * d);
        float so, co; sincosf(om, &so, &co);
        float sph, cph_; sincosf(pph, &sph, &cph_);
        float4 v = make_float4(pc * cph_, pc * sph, dec * co, dec * so);
        if (ch) g_pang[i * S + s] = v;
        else {
            g_plin[i * S + s] = v;
            int c8 = 8 * NI + i;
            g_base[i * S + s] = mn[0] + P[c8] + bias[c8];
        }
    }
}

// ---------------- 2) triangular sweep + fused final fold (R13/R15 form) ----
__device__ __forceinline__ void fold32(const ull* sbuf, float* pout, int lane) {
    const ull* row = sbuf + lane * 33;
    ull a0 = 0ULL, a1 = 0ULL, a2 = 0ULL, a3 = 0ULL;
    #pragma unroll
    for (int c = 0; c < 32; c += 4) {
        ull v0 = row[c + 0]; ADD2_IP(a0, v0);
        ull v1 = row[c + 1]; ADD2_IP(a1, v1);
        ull v2 = row[c + 2]; ADD2_IP(a2, v2);
        ull v3 = row[c + 3]; ADD2_IP(a3, v3);
    }
    ull u, v2s, acc;
    ADD2F(u, a0, a1);
    ADD2F(v2s, a2, a3);
    ADD2F(acc, u, v2s);
    float lo, hi; upk2(acc, lo, hi);
    pout[lane] = lo + hi;
}

__device__ __forceinline__ void run_full(int a0, int b0, int i, float* pout,
                                         int lane, ull* sbuf) {
    ull X[4], Y[4], CW[4], SW[4], CW2[4], SW2[4], NSW2[4];
    #pragma unroll
    for (int j = 0; j < 4; j++) {
        int a = a0 + j * 32 + lane;
        float4 pl = g_plin[i * S + a];
        float4 pa = g_pang[i * S + a];
        CW[j] = pk2(pl.z, pa.z);
        SW[j] = pk2(pl.w, pa.w);
        ull t2 = mul2(CW[j], SW[j]);
        CW2[j]  = fma2(CW[j], CW[j], neg2(mul2(SW[j], SW[j])));
        SW2[j]  = add2(t2, t2);
        NSW2[j] = neg2(SW2[j]);
        ull rx, ry;
        cpow2(CW[j], SW[j], (unsigned)(b0 - a), rx, ry);
        ull x0 = pk2(pl.x, pa.x), y0 = pk2(pl.y, pa.y);
        X[j] = fma2(x0, rx, neg2(mul2(y0, ry)));
        Y[j] = fma2(x0, ry, mul2(y0, rx));
    }
    #pragma unroll 1
    for (int chunk = 0; chunk < 4; chunk++) {
        #pragma unroll
        for (int it = 0; it < 16; it++) {
            int bb0 = it * 2;
            ull u01, u23, sA;
            ADD2F(u01, Y[0], Y[1]);
            ADD2F(u23, Y[2], Y[3]);
            ADD2F(sA, u01, u23);
            sbuf[bb0 * 33 + lane] = sA;
            ull m0, m1, m2, m3, v0, v1, v2, v3;
            MUL2F(m0, Y[0], CW[0]); FMA2F(v0, X[0], SW[0], m0);
            MUL2F(m1, Y[1], CW[1]); FMA2F(v1, X[1], SW[1], m1);
            MUL2F(m2, Y[2], CW[2]); FMA2F(v2, X[2], SW[2], m2);
            MUL2F(m3, Y[3], CW[3]); FMA2F(v3, X[3], SW[3], m3);
            ull w01, w23, sB;
            ADD2F(w01, v0, v1);
            ADD2F(w23, v2, v3);
            ADD2F(sB, w01, w23);
            sbuf[(bb0 + 1) * 33 + lane] = sB;
            #pragma unroll
            for (int j = 0; j < 4; j++) {
                ull t1, t2b;
                MUL2F(t1, Y[j], NSW2[j]);
                MUL2F(t2b, X[j], SW2[j]);
                asm("fma.rn.f32x2 %0, %0, %1, %2;" : "+l"(X[j]) : "l"(CW2[j]), "l"(t1));
                asm("fma.rn.f32x2 %0, %0, %1, %2;" : "+l"(Y[j]) : "l"(CW2[j]), "l"(t2b));
            }
        }
        __syncwarp();
        fold32(sbuf, pout + chunk * 32, lane);
        __syncwarp();
    }
}

__device__ __forceinline__ void run_diag(int b0, int i, float* pout,
                                         int lane, ull* sbuf) {
    ull X[4], Y[4], CW[4], SW[4], NSW[4], X0[4], Y0[4];
    int aj[4];
    #pragma unroll
    for (int j = 0; j < 4; j++) {
        int a = b0 + j * 32 + lane;
        aj[j] = a;
        float4 pl = g_plin[i * S + a];
        float4 pa = g_pang[i * S + a];
        CW[j]  = pk2(pl.z, pa.z);
        SW[j]  = pk2(pl.w, pa.w);
        NSW[j] = neg2(SW[j]);
        X0[j] = pk2(pl.x, pa.x);
        Y0[j] = pk2(pl.y, pa.y);
        X[j] = 0ULL; Y[j] = 0ULL;
    }
    #pragma unroll 1
    for (int chunk = 0; chunk < 4; chunk++) {
        #pragma unroll
        for (int bb = 0; bb < 32; bb++) {
            int b = b0 + chunk * 32 + bb;
            #pragma unroll
            for (int j = 0; j < 4; j++) {
                bool hit = (b == aj[j]);
                X[j] = hit ? X0[j] : X[j];
                Y[j] = hit ? Y0[j] : Y[j];
            }
            ull u01, u23, sA;
            ADD2F(u01, Y[0], Y[1]);
            ADD2F(u23, Y[2], Y[3]);
            ADD2F(sA, u01, u23);
            sbuf[bb * 33 + lane] = sA;
            #pragma unroll
            for (int j = 0; j < 4; j++) {
                ull t1, t2;
                MUL2F(t1, Y[j], NSW[j]);
                MUL2F(t2, X[j], SW[j]);
                asm("fma.rn.f32x2 %0, %0, %1, %2;" : "+l"(X[j]) : "l"(CW[j]), "l"(t1));
                asm("fma.rn.f32x2 %0, %0, %1, %2;" : "+l"(Y[j]) : "l"(CW[j]), "l"(t2));
            }
        }
        __syncwarp();
        fold32(sbuf, pout + chunk * 32, lane);
        __syncwarp();
    }
}

// grid (136, 13): slot -> (ca, cb) triangular, ca <= cb. Last tile of a
// (i, cb) column (cb+1 tiles) folds base + partials -> out, resets counter.
__global__ __launch_bounds__(32) void sweep_kernel(float* __restrict__ out) {
    __shared__ ull sbuf[32 * 33];   // 8448 B
    int slot = blockIdx.x, i = blockIdx.y;
    int lane = threadIdx.x;
    int s = slot, cb = 0;
    while (s > cb) { s -= (cb + 1); cb++; }
    int ca = s;
    float* pout = g_partial + (ca * NI + i) * S + cb * 128;
    if (ca == cb) run_diag(cb * 128, i, pout, lane, sbuf);
    else          run_full(ca * 128, cb * 128, i, pout, lane, sbuf);

    __threadfence();
    int last = 0;
    if (lane == 0)
        last = (atomicAdd(&g_cnt[i * 16 + cb], 1) == cb);
    last = __shfl_sync(0xffffffffu, last, 0);
    if (last) {
        __threadfence();
        #pragma unroll
        for (int g = 0; g < 4; g++) {
            int b = cb * 128 + g * 32 + lane;
            float acc = g_base[i * S + b];
            #pragma unroll
            for (int c2 = 0; c2 < 16; c2++)
                if (c2 <= cb) acc += g_partial[(c2 * NI + i) * S + b];
            out[i * S + b] = acc;
        }
        if (lane == 0) g_cnt[i * 16 + cb] = 0;   // self-reset for next replay
    }
}

// ---------------- launch ----------------
extern "C" void kernel_launch(void* const* d_in, const int* in_sizes, int n_in,
                              void* d_out, int out_size) {
    const float* h    = (const float*)d_in[0];
    const float* mn   = (const float*)d_in[1];
    const float* lw   = (const float*)d_in[2];
    const float* lb   = (const float*)d_in[3];
    const float* W    = (const float*)d_in[4];
    const float* bias = (const float*)d_in[5];
    float* out = (float*)d_out;

    wprep_kernel<<<64, 256>>>(W);
    gemm_fused<<<S / 16, 512>>>(h, mn, lw, lb, bias);
    dim3 g(136, NI);
    sweep_kernel<<<g, 32>>>(out);
}